// round 4
// baseline (speedup 1.0000x reference)
#include <cuda_runtime.h>
#include <math.h>

// Problem dims (fixed by the dataset)
#define BB 2
#define DD 64
#define HH 128
#define WW 128
#define HW (HH*WW)
#define SP (DD*HW)     // 1,048,576 per batch
#define NT (BB*SP)     // 2,097,152 total voxels

#define TH 8           // H rows per block
#define CHUNK 8        // D planes per block sweep (legacy k_minacc)
#define SCH 16         // D planes per block sweep (fused kernels)
#define INFF __int_as_float(0x7f800000)
#define NINFF (-__int_as_float(0x7f800000))

// ---------------- scratch fields (__device__ globals: allocation-free) ------
__device__ __align__(16) float g_P[NT];        // prob
__device__ __align__(16) float g_Y[NT];        // y_true
__device__ __align__(16) float g_H[NT];        // hard
__device__ __align__(16) float g_S[3*NT];      // skel outputs: P, T(y), H
__device__ __align__(16) float g_A[3*NT];      // skel chain ping
__device__ __align__(16) float g_B[3*NT];      // skel chain pong
__device__ __align__(16) float g_EA[2*NT];     // edt ping (Y, H)
__device__ __align__(16) float g_EB[2*NT];     // edt pong
__device__ __align__(16) float g_ACC[2*NT];    // edt acc (L, P)

// sums: 0 p1, 1 y, 2 p1*y, 3 ce, 4 conn, 5 dir,
//       6 skelP*y, 7 skelP, 8 skelT*p, 9 skelT,
//       10 inter1, 11 union1, 12 inter2, 13 union2
__device__ double g_sum[14];
__device__ unsigned g_rmx[4];
__device__ unsigned g_rmn[4];

// ---------------- small helpers ---------------------------------------------
template<bool MIN>
__device__ __forceinline__ float opf(float a, float b) { return MIN ? fminf(a, b) : fmaxf(a, b); }

template<bool MIN>
__device__ __forceinline__ float4 op4(float4 a, float4 b) {
    float4 o;
    o.x = opf<MIN>(a.x, b.x); o.y = opf<MIN>(a.y, b.y);
    o.z = opf<MIN>(a.z, b.z); o.w = opf<MIN>(a.w, b.w);
    return o;
}

template<bool MIN>
__device__ __forceinline__ float4 ident4() {
    float v = MIN ? INFF : NINFF;
    return make_float4(v, v, v, v);
}

// 1-D pool over W inside one warp (each lane owns 4 consecutive w)
template<bool MIN>
__device__ __forceinline__ float4 wpool(float4 v, int lane) {
    float idv = MIN ? INFF : NINFF;
    float l = __shfl_up_sync(0xffffffffu, v.w, 1);
    float r = __shfl_down_sync(0xffffffffu, v.x, 1);
    if (lane == 0) l = idv;
    if (lane == 31) r = idv;
    float4 o;
    o.x = opf<MIN>(opf<MIN>(l, v.x), v.y);
    o.y = opf<MIN>(opf<MIN>(v.x, v.y), v.z);
    o.z = opf<MIN>(opf<MIN>(v.y, v.z), v.w);
    o.w = opf<MIN>(opf<MIN>(v.z, v.w), r);
    return o;
}

// shift value array by +1 element (result[i] = a[i+1]); OOB = +INF
__device__ __forceinline__ float4 shl1_min(float4 a, int lane) {
    float nx = __shfl_down_sync(0xffffffffu, a.x, 1);
    if (lane == 31) nx = INFF;
    return make_float4(a.y, a.z, a.w, nx);
}
// shift by -1 (result[i] = a[i-1]); OOB = +INF
__device__ __forceinline__ float4 shr1_min(float4 a, int lane) {
    float pw = __shfl_up_sync(0xffffffffu, a.w, 1);
    if (lane == 0) pw = INFF;
    return make_float4(pw, a.x, a.y, a.z);
}

// compute W+H pooled plane value for this thread's (row, lanes) at depth d
template<bool MIN>
__device__ __forceinline__ float4 plane_wh(const float* __restrict__ src, int h0, int d,
                                           int lane, int ty, float4* sm, int buf) {
    float4 id4 = ident4<MIN>();
    float4* S = sm + buf * ((TH + 2) * 32);
    if (d >= 0 && d < DD) {
        const float4* p = (const float4*)(src + (size_t)d * HW);
        float4 v = p[(h0 + ty) * 32 + lane];
        S[(ty + 1) * 32 + lane] = wpool<MIN>(v, lane);
        if (ty == 0)
            S[lane] = (h0 - 1 >= 0) ? wpool<MIN>(p[(h0 - 1) * 32 + lane], lane) : id4;
        if (ty == TH - 1)
            S[(TH + 1) * 32 + lane] = (h0 + TH < HH) ? wpool<MIN>(p[(h0 + TH) * 32 + lane], lane) : id4;
    }
    __syncthreads();
    if (d < 0 || d >= DD) return id4;
    float4 a = S[ty * 32 + lane];
    float4 b = S[(ty + 1) * 32 + lane];
    float4 c = S[(ty + 2) * 32 + lane];
    return op4<MIN>(op4<MIN>(a, b), c);
}

// ---------------- fused skeleton step ----------------------------------------
// One soft_skel iteration: e = erode(src) [written], dil = dilate27(e),
// delta = relu(src - dil), skel update. Batched over grid.z = 3 fields x batch.
__global__ void __launch_bounds__(256) k_skel_step(const float* __restrict__ src_base,
                                                   float* __restrict__ e_base,
                                                   float* __restrict__ skel_base,
                                                   int first) {
    __shared__ float4 rawv[4][TH + 4][32];   // raw src plane ring (rows h0-2..h0+TH+1)
    __shared__ float4 wpe[2][TH + 2][32];    // w-pooled(max) e rows (h0-1..h0+TH)
    int lane = threadIdx.x, ty = threadIdx.y;
    int h0 = blockIdx.x * TH;
    int dz = blockIdx.y * SCH;
    int f = blockIdx.z >> 1, b = blockIdx.z & 1;
    size_t off = (size_t)f * NT + (size_t)b * SP;
    const float* src = src_base + off;
    float* edst = e_base + off;
    float* skel = skel_base + off;

    const float4 INF4  = make_float4(INFF, INFF, INFF, INFF);
    const float4 NINF4 = make_float4(NINFF, NINFF, NINFF, NINFF);
    float4 we3[3]; we3[0] = NINF4; we3[1] = NINF4; we3[2] = NINF4;
    int par = 0;

    for (int lp = dz - 2; lp <= dz + SCH + 1; lp++) {
        int slot = (lp + 8) & 3;
        bool pv = (lp >= 0 && lp < DD);
        // --- store raw plane lp (center row + 4 halo rows) ---
        {
            int gh = h0 + ty;
            rawv[slot][ty + 2][lane] = pv ?
                ((const float4*)(src + (size_t)lp * HW))[gh * 32 + lane] : INF4;
        }
        if (ty < 4) {
            int gh = (ty < 2) ? (h0 - 2 + ty) : (h0 + TH + (ty - 2));
            int sr = (ty < 2) ? ty : (TH + 2 + (ty - 2));
            float4 v = INF4;
            if (pv && (unsigned)gh < HH)
                v = ((const float4*)(src + (size_t)lp * HW))[gh * 32 + lane];
            rawv[slot][sr][lane] = v;
        }
        __syncthreads();

        // --- compute e(ep) rows [h0-1, h0+TH], write center rows, wpool(max) ---
        int ep = lp - 1;
        bool epv = (ep >= 0 && ep < DD);
        bool estep = (ep >= dz - 1);
        if (estep) {
            int s1 = (ep + 8) & 3, s0 = (ep + 7) & 3, s2 = (ep + 9) & 3;
            {   // center row
                if (epv) {
                    int sr = ty + 2;
                    float4 vC = rawv[s1][sr][lane];
                    float4 c = op4<true>(wpool<true>(vC, lane),
                                op4<true>(rawv[s1][sr - 1][lane], rawv[s1][sr + 1][lane]));
                    float4 e = op4<true>(c, op4<true>(rawv[s0][sr][lane], rawv[s2][sr][lane]));
                    if (ep >= dz && ep < dz + SCH)
                        ((float4*)edst)[(size_t)ep * (HW / 4) + (h0 + ty) * 32 + lane] = e;
                    wpe[par][ty + 1][lane] = wpool<false>(e, lane);
                } else {
                    wpe[par][ty + 1][lane] = NINF4;
                }
            }
            if (ty == 0 || ty == TH - 1) {   // H-halo e rows
                int gh = (ty == 0) ? (h0 - 1) : (h0 + TH);
                int sr = (ty == 0) ? 1 : (TH + 2);
                int wr = (ty == 0) ? 0 : (TH + 1);
                if (epv && (unsigned)gh < HH) {
                    float4 vC = rawv[s1][sr][lane];
                    float4 c = op4<true>(wpool<true>(vC, lane),
                                op4<true>(rawv[s1][sr - 1][lane], rawv[s1][sr + 1][lane]));
                    float4 e = op4<true>(c, op4<true>(rawv[s0][sr][lane], rawv[s2][sr][lane]));
                    wpe[par][wr][lane] = wpool<false>(e, lane);
                } else {
                    wpe[par][wr][lane] = NINF4;
                }
            }
        }
        __syncthreads();

        // --- H-pool(max) of wpe -> whmax_e(ep) into register ring ---
        if (estep) {
            float4 we = NINF4;
            if (epv)
                we = op4<false>(op4<false>(wpe[par][ty][lane], wpe[par][ty + 1][lane]),
                                wpe[par][ty + 2][lane]);
            we3[(ep + 9) % 3] = we;
            par ^= 1;
        }

        // --- skel update at plane d = lp-2 ---
        int d = lp - 2;
        if (d >= dz && d < dz + SCH) {
            float4 dil = op4<false>(op4<false>(we3[0], we3[1]), we3[2]);
            float4 vd = rawv[(d + 8) & 3][ty + 2][lane];
            float4 dl;
            dl.x = fmaxf(vd.x - dil.x, 0.f); dl.y = fmaxf(vd.y - dil.y, 0.f);
            dl.z = fmaxf(vd.z - dil.z, 0.f); dl.w = fmaxf(vd.w - dil.w, 0.f);
            size_t ro = (size_t)d * (HW / 4) + (h0 + ty) * 32 + lane;
            if (first) {
                ((float4*)skel)[ro] = dl;
            } else {
                float4 s = ((float4*)skel)[ro];
                s.x += fmaxf(dl.x - s.x * dl.x, 0.f);
                s.y += fmaxf(dl.y - s.y * dl.y, 0.f);
                s.z += fmaxf(dl.z - s.z * dl.z, 0.f);
                s.w += fmaxf(dl.w - s.w * dl.w, 0.f);
                ((float4*)skel)[ro] = s;
            }
        }
    }
}

// ---------------- fused 2-level EDT step --------------------------------------
// e1 = minpool3^1(src), e2 = minpool3^2(src) = minpool5(src) (separable, exact).
// acc += e1 + e2; dst = e2. Batched over grid.z = 2 fields x batch.
__global__ void __launch_bounds__(256) k_edt2(const float* __restrict__ src_base,
                                              float* __restrict__ dst_base,
                                              float* __restrict__ acc_base) {
    __shared__ float4 w3s[2][TH + 4][32];
    __shared__ float4 w5s[2][TH + 4][32];
    int lane = threadIdx.x, ty = threadIdx.y;
    int h0 = blockIdx.x * TH;
    int dz = blockIdx.y * SCH;
    int f = blockIdx.z >> 1, b = blockIdx.z & 1;
    size_t off = (size_t)f * NT + (size_t)b * SP;
    const float* src = src_base + off;
    float* dst = dst_base + off;
    float* acc = acc_base + off;

    const float4 INF4 = make_float4(INFF, INFF, INFF, INFF);
    float4 P3r[4], P5r[5];
    int par = 0;

    for (int lp = dz - 2; lp <= dz + SCH + 1; lp++) {
        bool pv = (lp >= 0 && lp < DD);
        if (pv) {
            {   // center row
                int gh = h0 + ty;
                float4 v = ((const float4*)(src + (size_t)lp * HW))[gh * 32 + lane];
                float4 a3 = wpool<true>(v, lane);
                float4 a5 = op4<true>(shl1_min(a3, lane), shr1_min(a3, lane));
                w3s[par][ty + 2][lane] = a3;
                w5s[par][ty + 2][lane] = a5;
            }
            if (ty < 4) {   // halo rows
                int gh = (ty < 2) ? (h0 - 2 + ty) : (h0 + TH + (ty - 2));
                int sr = (ty < 2) ? ty : (TH + 2 + (ty - 2));
                float4 v = INF4;
                if ((unsigned)gh < HH)
                    v = ((const float4*)(src + (size_t)lp * HW))[gh * 32 + lane];
                float4 a3 = wpool<true>(v, lane);
                float4 a5 = op4<true>(shl1_min(a3, lane), shr1_min(a3, lane));
                w3s[par][sr][lane] = a3;
                w5s[par][sr][lane] = a5;
            }
        }
        __syncthreads();
        float4 P3 = INF4, P5 = INF4;
        if (pv) {
            P3 = op4<true>(op4<true>(w3s[par][ty + 1][lane], w3s[par][ty + 2][lane]),
                           w3s[par][ty + 3][lane]);
            P5 = op4<true>(op4<true>(w5s[par][ty][lane], w5s[par][ty + 1][lane]),
                 op4<true>(w5s[par][ty + 2][lane],
                 op4<true>(w5s[par][ty + 3][lane], w5s[par][ty + 4][lane])));
        }
        par ^= 1;
        P3r[(lp + 8) & 3] = P3;
        P5r[(lp + 10) % 5] = P5;

        int d = lp - 2;
        if (d >= dz && d < dz + SCH) {
            float4 e1 = op4<true>(op4<true>(P3r[(d + 7) & 3], P3r[(d + 8) & 3]),
                                  P3r[(d + 9) & 3]);
            float4 e2 = op4<true>(op4<true>(P5r[(d + 8) % 5], P5r[(d + 9) % 5]),
                        op4<true>(P5r[(d + 10) % 5],
                        op4<true>(P5r[(d + 11) % 5], P5r[(d + 12) % 5])));
            size_t ro = (size_t)d * (HW / 4) + (h0 + ty) * 32 + lane;
            ((float4*)dst)[ro] = e2;
            float4 av = ((float4*)acc)[ro];
            av.x += e1.x + e2.x; av.y += e1.y + e2.y;
            av.z += e1.z + e2.z; av.w += e1.w + e2.w;
            ((float4*)acc)[ro] = av;
        }
    }
}

// ---------------- legacy single-level minpool + acc (final EDT iteration) ----
__global__ void __launch_bounds__(256) k_minacc(const float* __restrict__ src_base,
                                                float* __restrict__ dst_base,
                                                float* __restrict__ acc_base) {
    __shared__ float4 sm[2 * (TH + 2) * 32];
    int lane = threadIdx.x, ty = threadIdx.y;
    int h0 = blockIdx.x * TH;
    int dz = blockIdx.y * CHUNK;
    int f = blockIdx.z >> 1, b = blockIdx.z & 1;
    size_t off = (size_t)f * NT + (size_t)b * SP;
    const float* src = src_base + off;
    float* dst = dst_base + off;
    float* acc = acc_base + off;

    int buf = 0;
    float4 pa = plane_wh<true>(src, h0, dz - 1, lane, ty, sm, buf); buf ^= 1;
    float4 pb = plane_wh<true>(src, h0, dz,     lane, ty, sm, buf); buf ^= 1;
    for (int d = dz; d < dz + CHUNK; d++) {
        float4 pc = plane_wh<true>(src, h0, d + 1, lane, ty, sm, buf); buf ^= 1;
        float4 o = op4<true>(op4<true>(pa, pb), pc);
        size_t ro = (size_t)d * (HW / 4) + (h0 + ty) * 32 + lane;
        ((float4*)dst)[ro] = o;
        float4 av = ((float4*)acc)[ro];
        av.x += o.x; av.y += o.y; av.z += o.z; av.w += o.w;
        ((float4*)acc)[ro] = av;
        pa = pb; pb = pc;
    }
}

// ---------------- reduction helpers (256-thread blocks) ---------------------
__device__ __forceinline__ int flat_tid() { return threadIdx.y * blockDim.x + threadIdx.x; }

__device__ __forceinline__ void block_add(double v, double* dst) {
    int tid = flat_tid();
    for (int o = 16; o; o >>= 1) v += __shfl_down_sync(0xffffffffu, v, o);
    __shared__ double sh[8];
    int lane = tid & 31, wid = tid >> 5;
    if (lane == 0) sh[wid] = v;
    __syncthreads();
    if (wid == 0) {
        double x = (lane < 8) ? sh[lane] : 0.0;
        for (int o = 4; o; o >>= 1) x += __shfl_down_sync(0xffffffffu, x, o);
        if (lane == 0) atomicAdd(dst, x);
    }
    __syncthreads();
}

__device__ __forceinline__ float block_maxv(float v) {
    int tid = flat_tid();
    for (int o = 16; o; o >>= 1) v = fmaxf(v, __shfl_down_sync(0xffffffffu, v, o));
    __shared__ float sh[8];
    int lane = tid & 31, wid = tid >> 5;
    if (lane == 0) sh[wid] = v;
    __syncthreads();
    float r = v;
    if (wid == 0) {
        float x = (lane < 8) ? sh[lane] : -1e30f;
        for (int o = 4; o; o >>= 1) x = fmaxf(x, __shfl_down_sync(0xffffffffu, x, o));
        r = x;
    }
    __syncthreads();
    return r;
}

__device__ __forceinline__ float block_minv(float v) {
    int tid = flat_tid();
    for (int o = 16; o; o >>= 1) v = fminf(v, __shfl_down_sync(0xffffffffu, v, o));
    __shared__ float sh[8];
    int lane = tid & 31, wid = tid >> 5;
    if (lane == 0) sh[wid] = v;
    __syncthreads();
    float r = v;
    if (wid == 0) {
        float x = (lane < 8) ? sh[lane] : 1e30f;
        for (int o = 4; o; o >>= 1) x = fminf(x, __shfl_down_sync(0xffffffffu, x, o));
        r = x;
    }
    __syncthreads();
    return r;
}

// ---------------- pointwise / reduction kernels -------------------------------
__global__ void k_zero() {
    int t = threadIdx.x;
    if (t < 14) g_sum[t] = 0.0;
    if (t < 4) { g_rmx[t] = 0u; g_rmn[t] = 0x7f800000u; }
}

__global__ void k_init(const float* __restrict__ net, const int* __restrict__ tgt) {
    int i = blockIdx.x * blockDim.x + threadIdx.x;
    int b = i / SP, s = i - b * SP;
    float x0 = net[(size_t)(b * 2) * SP + s];
    float x1 = net[(size_t)(b * 2 + 1) * SP + s];
    int t = tgt[i];
    float m = fmaxf(x0, x1);
    float e0 = expf(x0 - m), e1 = expf(x1 - m);
    float z = e0 + e1;
    float p1 = e1 / z;
    float yv = (t > 0) ? 1.f : 0.f;
    float hd = (p1 > 0.5f) ? 1.f : 0.f;
    g_P[i] = p1; g_Y[i] = yv; g_H[i] = hd;
    g_A[i] = p1; g_A[NT + i] = yv; g_A[2 * NT + i] = hd;
    float lse = m + logf(z);
    float ce = -(((t > 0) ? x1 : x0) - lse);
    float conn = fabsf(((x0 > 0.5f) ? 1.f : 0.f) - yv) + fabsf(((x1 > 0.5f) ? 1.f : 0.f) - yv);
    block_add((double)p1,        &g_sum[0]);
    block_add((double)yv,        &g_sum[1]);
    block_add((double)(p1 * yv), &g_sum[2]);
    block_add((double)ce,        &g_sum[3]);
    block_add((double)conn,      &g_sum[4]);
}

__global__ void k_edtinit() {
    int i = blockIdx.x * blockDim.x + threadIdx.x;  // i in [0, 2*NT)
    float v = (i < NT) ? g_Y[i] : g_H[i - NT];
    g_EA[i] = v;
    g_ACC[i] = v;
}

__global__ void k_sobel(const float* __restrict__ net, const int* __restrict__ tgt) {
    int w = blockIdx.x * blockDim.x + threadIdx.x;
    int h = blockIdx.y * blockDim.y + threadIdx.y;
    int z = blockIdx.z;
    int b = z / DD, d = z - b * DD;
    const float smw[3] = {1.f, 2.f, 1.f};
    const float grw[3] = {-1.f, 0.f, 1.f};
    float gx = 0.f, gy = 0.f, gz = 0.f, tx = 0.f, ty = 0.f, tz = 0.f;
    const float* p0 = net + (size_t)(b * 2) * SP;
    const int*   tb = tgt + (size_t)b * SP;
    #pragma unroll
    for (int dd = -1; dd <= 1; dd++) {
        int dn = d + dd; if (dn < 0 || dn >= DD) continue;
        #pragma unroll
        for (int hh = -1; hh <= 1; hh++) {
            int hn = h + hh; if (hn < 0 || hn >= HH) continue;
            #pragma unroll
            for (int ww = -1; ww <= 1; ww++) {
                int wn = w + ww; if (wn < 0 || wn >= WW) continue;
                int o = dn * HW + hn * WW + wn;
                float v  = p0[o];
                float tv = (float)tb[o];
                float ca = smw[hh + 1] * grw[ww + 1];
                float cb = smw[dd + 1] * grw[ww + 1];
                float cc = smw[dd + 1] * grw[hh + 1];
                gx += v * ca;  gy += v * cb;  gz += v * cc;
                tx += tv * ca; ty += tv * cb; tz += tv * cc;
            }
        }
    }
    float npn = sqrtf(gx * gx + gy * gy + gz * gz);
    float ia = 1.f / fmaxf(npn, 1e-12f);
    float px = gx * ia, py = gy * ia, pz = gz * ia;
    float ntn = sqrtf(tx * tx + ty * ty + tz * tz);
    float ib = 1.f / fmaxf(ntn, 1e-12f);
    float qx = tx * ib, qy = ty * ib, qz = tz * ib;
    float num = px * qx + py * qy + pz * qz;
    float den = fmaxf(sqrtf(px * px + py * py + pz * pz) *
                      sqrtf(qx * qx + qy * qy + qz * qz), 1e-8f);
    block_add((double)(num / den), &g_sum[5]);
}

__global__ void k_radius() {
    int i = blockIdx.x * 256 + threadIdx.x;
    int b = i / SP;
    float radl = g_ACC[i] * g_Y[i] * g_S[NT + i];
    float spp  = g_S[2 * NT + i] * g_P[i];
    float sb   = (spp > 0.5f) ? 1.f : 0.f;
    float radp = g_ACC[NT + i] * g_H[i] * sb;
    float mxl = block_maxv(radl);
    float mnl = block_minv(radl);
    float mxp = block_maxv(radp);
    float mnp = block_minv(radp);
    if (flat_tid() == 0) {
        atomicMax(&g_rmx[b],     __float_as_uint(mxl));
        atomicMin(&g_rmn[b],     __float_as_uint(mnl));
        atomicMax(&g_rmx[2 + b], __float_as_uint(mxp));
        atomicMin(&g_rmn[2 + b], __float_as_uint(mnp));
    }
}

__global__ void k_final() {
    int i = blockIdx.x * 256 + threadIdx.x;
    int b = i / SP;
    float spv = g_S[i];
    float st  = g_S[NT + i];
    float y   = g_Y[i];
    float p   = g_P[i];
    float hd  = g_H[i];
    float sh  = g_S[2 * NT + i];

    float rmaxl = fmaxf(__uint_as_float(g_rmx[b]), 1.f);
    float rminl = fmaxf(__uint_as_float(g_rmn[b]), 1.f);
    float rmaxp = fmaxf(__uint_as_float(g_rmx[2 + b]), 1.f);
    float rminp = fmaxf(__uint_as_float(g_rmn[2 + b]), 1.f);

    float distl = g_ACC[i] * y;
    float qvl = fminf(distl, rmaxl) / rmaxl * y;
    float radl = distl * st;
    float il = (rmaxl - radl + rminl) / rmaxl; il *= il;
    float qsl = il * st * st;

    float spp = sh * p;
    float sb  = (spp > 0.5f) ? 1.f : 0.f;
    float distp = g_ACC[NT + i] * hd;
    float qvp = fminf(distp, rmaxp) / rmaxp * p;
    float radp = distp * sb;
    float ip = (rmaxp - radp + rminp) / rmaxp; ip *= ip;
    float qsp = ip * sb * spp;

    float inter1 = qsp * powf(qsp + 1e-4f, 0.7f) * qvl;
    float union1 = qsp * (0.1f * qsp + 0.9f * qvl);
    float inter2 = qsl * powf(qvp + 1e-4f, 0.7f) * qsl;
    float union2 = qsl * (0.1f * qvp + 0.9f * qsl);

    block_add((double)(spv * y), &g_sum[6]);
    block_add((double)spv,       &g_sum[7]);
    block_add((double)(st * p),  &g_sum[8]);
    block_add((double)st,        &g_sum[9]);
    block_add((double)inter1,    &g_sum[10]);
    block_add((double)union1,    &g_sum[11]);
    block_add((double)inter2,    &g_sum[12]);
    block_add((double)union2,    &g_sum[13]);
}

__global__ void k_combine(float* out) {
    double tp = g_sum[2];
    double fp = g_sum[0] - tp;
    double fn = g_sum[1] - tp;
    double dice = -((2.0 * tp + 1e-5) / (2.0 * tp + fp + fn + 1e-5));
    double ce   = g_sum[3] / (double)NT;
    double tprec = (g_sum[6] + 1.0) / (g_sum[7] + 1.0);
    double tsens = (g_sum[8] + 1.0) / (g_sum[9] + 1.0);
    double cl = 1.0 - 2.0 * tprec * tsens / (tprec + tsens);
    double dir  = 1.0 - g_sum[5] / (double)NT;
    double conn = g_sum[4] / (2.0 * (double)NT);
    double u1 = 1.0 - (g_sum[10] + 1.0) / (g_sum[11] + 1.0);
    double u2 = 1.0 - (g_sum[12] + 1.0) / (g_sum[13] + 1.0);
    out[0] = (float)(dice + ce + cl + dir + conn + u1 + u2);
}

// ---------------- host orchestration ----------------------------------------
extern "C" void kernel_launch(void* const* d_in, const int* in_sizes, int n_in,
                              void* d_out, int out_size) {
    (void)in_sizes; (void)n_in; (void)out_size;
    const float* net = (const float*)d_in[0];
    const int*   tgt = (const int*)d_in[1];
    float* out = (float*)d_out;

    float *A, *Bp, *S, *EA, *EB, *ACC;
    cudaGetSymbolAddress((void**)&A,   g_A);
    cudaGetSymbolAddress((void**)&Bp,  g_B);
    cudaGetSymbolAddress((void**)&S,   g_S);
    cudaGetSymbolAddress((void**)&EA,  g_EA);
    cudaGetSymbolAddress((void**)&EB,  g_EB);
    cudaGetSymbolAddress((void**)&ACC, g_ACC);

    dim3 blk(32, TH, 1);
    dim3 grdS(HH / TH, DD / SCH, 3 * BB);    // fused skel: 16 x 4 x 6 = 384 blocks
    dim3 grdE(HH / TH, DD / SCH, 2 * BB);    // fused edt:  16 x 4 x 4 = 256 blocks
    dim3 grdM(HH / TH, DD / CHUNK, 2 * BB);  // legacy minacc
    dim3 sblk(32, 8, 1), sgrd(WW / 32, HH / 8, BB * DD);

    k_zero<<<1, 32>>>();
    k_init<<<NT / 256, 256>>>(net, tgt);
    k_sobel<<<sgrd, sblk>>>(net, tgt);

    // three soft_skels batched: 11 fused iterations
    float* cur = A; float* oth = Bp;
    for (int it = 0; it < 11; it++) {
        k_skel_step<<<grdS, blk>>>(cur, oth, S, it == 0);
        float* t = cur; cur = oth; oth = t;
    }

    // two EDT scans batched: 7 fused double iterations + 1 single
    k_edtinit<<<2 * NT / 256, 256>>>();
    float* ec = EA; float* eo = EB;
    for (int j = 0; j < 7; j++) {
        k_edt2<<<grdE, blk>>>(ec, eo, ACC);
        float* t = ec; ec = eo; eo = t;
    }
    k_minacc<<<grdM, blk>>>(ec, eo, ACC);

    k_radius<<<NT / 256, 256>>>();
    k_final<<<NT / 256, 256>>>();
    k_combine<<<1, 1>>>(out);
}

// round 5
// speedup vs baseline: 1.0237x; 1.0237x over previous
#include <cuda_runtime.h>
#include <math.h>

// Problem dims (fixed by the dataset)
#define BB 2
#define DD 64
#define HH 128
#define WW 128
#define HW (HH*WW)
#define SP (DD*HW)     // 1,048,576 per batch
#define NT (BB*SP)     // 2,097,152 total voxels

#define TH 8           // H rows per block
#define CHUNK 8        // D planes per block sweep
#define INFF __int_as_float(0x7f800000)
#define NINFF (-__int_as_float(0x7f800000))

// ---------------- scratch fields (__device__ globals: allocation-free) ------
__device__ __align__(16) float g_P[NT];        // prob
__device__ __align__(16) float g_Y[NT];        // y_true
__device__ __align__(16) float g_H[NT];        // hard
__device__ __align__(16) float g_S[3*NT];      // skel outputs: P, T(y), H
__device__ __align__(16) float g_A[3*NT];      // skel chain ping
__device__ __align__(16) float g_B[3*NT];      // skel chain pong
__device__ __align__(16) float g_EA[2*NT];     // edt ping (Y, H)
__device__ __align__(16) float g_EB[2*NT];     // edt pong
__device__ __align__(16) float g_ACC[2*NT];    // edt acc (L, P)

// sums: 0 p1, 1 y, 2 p1*y, 3 ce, 4 conn, 5 dir,
//       6 skelP*y, 7 skelP, 8 skelT*p, 9 skelT,
//       10 inter1, 11 union1, 12 inter2, 13 union2
__device__ double g_sum[14];
__device__ unsigned g_rmx[4];
__device__ unsigned g_rmn[4];

// ---------------- small helpers ---------------------------------------------
template<bool MIN>
__device__ __forceinline__ float opf(float a, float b) { return MIN ? fminf(a, b) : fmaxf(a, b); }

template<bool MIN>
__device__ __forceinline__ float4 op4(float4 a, float4 b) {
    float4 o;
    o.x = opf<MIN>(a.x, b.x); o.y = opf<MIN>(a.y, b.y);
    o.z = opf<MIN>(a.z, b.z); o.w = opf<MIN>(a.w, b.w);
    return o;
}

template<bool MIN>
__device__ __forceinline__ float4 ident4() {
    float v = MIN ? INFF : NINFF;
    return make_float4(v, v, v, v);
}

// 1-D pool over W inside one warp (each lane owns 4 consecutive w)
template<bool MIN>
__device__ __forceinline__ float4 wpool(float4 v, int lane) {
    float idv = MIN ? INFF : NINFF;
    float l = __shfl_up_sync(0xffffffffu, v.w, 1);
    float r = __shfl_down_sync(0xffffffffu, v.x, 1);
    if (lane == 0) l = idv;
    if (lane == 31) r = idv;
    float4 o;
    o.x = opf<MIN>(opf<MIN>(l, v.x), v.y);
    o.y = opf<MIN>(opf<MIN>(v.x, v.y), v.z);
    o.z = opf<MIN>(opf<MIN>(v.y, v.z), v.w);
    o.w = opf<MIN>(opf<MIN>(v.z, v.w), r);
    return o;
}

// store a RAW plane (with H halo rows) into a ring buffer slot
__device__ __forceinline__ void store_raw(const float* __restrict__ src, int lp,
                                          float4 (*buf)[32], int h0, int lane, int ty) {
    const float4 id4 = make_float4(INFF, INFF, INFF, INFF);
    bool pv = (lp >= 0 && lp < DD);
    const float4* p = (const float4*)(src + (size_t)lp * HW);
    buf[ty + 1][lane] = pv ? p[(h0 + ty) * 32 + lane] : id4;
    if (ty == 0)
        buf[0][lane] = (pv && h0 > 0) ? p[(h0 - 1) * 32 + lane] : id4;
    if (ty == TH - 1)
        buf[TH + 1][lane] = (pv && h0 + TH < HH) ? p[(h0 + TH) * 32 + lane] : id4;
}

// store a W-POOLED plane (with H halo rows) into a ring buffer slot
template<bool MIN>
__device__ __forceinline__ void store_wp(const float* __restrict__ src, int lp,
                                         float4 (*buf)[32], int h0, int lane, int ty) {
    float4 id4 = ident4<MIN>();
    bool pv = (lp >= 0 && lp < DD);
    const float4* p = (const float4*)(src + (size_t)lp * HW);
    float4 v = pv ? p[(h0 + ty) * 32 + lane] : id4;
    buf[ty + 1][lane] = wpool<MIN>(v, lane);
    if (ty == 0)
        buf[0][lane] = (pv && h0 > 0) ? wpool<MIN>(p[(h0 - 1) * 32 + lane], lane) : id4;
    if (ty == TH - 1)
        buf[TH + 1][lane] = (pv && h0 + TH < HH) ? wpool<MIN>(p[(h0 + TH) * 32 + lane], lane) : id4;
}

template<bool MIN>
__device__ __forceinline__ float4 hpool3(float4 (*buf)[32], int lane, int ty) {
    return op4<MIN>(op4<MIN>(buf[ty][lane], buf[ty + 1][lane]), buf[ty + 2][lane]);
}

// ---------------- sweep kernels (D-unrolled by 2, 1 sync per 2 planes) -------
// soft_erode: 7-point cross min. grid.z = field*2 + batch (3 fields).
__global__ void __launch_bounds__(256) k_erode(const float* __restrict__ src_base,
                                               float* __restrict__ dst_base) {
    __shared__ float4 r[6][TH + 2][32];   // raw plane ring, slot = (plane+6)%6
    int lane = threadIdx.x, ty = threadIdx.y;
    int h0 = blockIdx.x * TH;
    int dz = blockIdx.y * CHUNK;
    int f = blockIdx.z >> 1, b = blockIdx.z & 1;
    size_t off = (size_t)f * NT + (size_t)b * SP;
    const float* src = src_base + off;
    float* dst = dst_base + off;

    store_raw(src, dz - 1, r[(dz + 5) % 6], h0, lane, ty);
    store_raw(src, dz,     r[dz % 6],       h0, lane, ty);
    #pragma unroll
    for (int k = 0; k < CHUNK; k += 2) {
        int d = dz + k;
        store_raw(src, d + 1, r[(d + 1) % 6], h0, lane, ty);
        store_raw(src, d + 2, r[(d + 2) % 6], h0, lane, ty);
        __syncthreads();
        // output d
        {
            float4 (*c1)[32] = r[d % 6];
            float4 a = c1[ty][lane], v = c1[ty + 1][lane], c = c1[ty + 2][lane];
            float4 vm = r[(d + 5) % 6][ty + 1][lane];
            float4 vp = r[(d + 1) % 6][ty + 1][lane];
            float4 o = op4<true>(wpool<true>(v, lane),
                      op4<true>(op4<true>(a, c), op4<true>(vm, vp)));
            ((float4*)dst)[(size_t)d * (HW / 4) + (h0 + ty) * 32 + lane] = o;
        }
        // output d+1
        {
            float4 (*c1)[32] = r[(d + 1) % 6];
            float4 a = c1[ty][lane], v = c1[ty + 1][lane], c = c1[ty + 2][lane];
            float4 vm = r[d % 6][ty + 1][lane];
            float4 vp = r[(d + 2) % 6][ty + 1][lane];
            float4 o = op4<true>(wpool<true>(v, lane),
                      op4<true>(op4<true>(a, c), op4<true>(vm, vp)));
            ((float4*)dst)[(size_t)(d + 1) * (HW / 4) + (h0 + ty) * 32 + lane] = o;
        }
    }
}

// dilate27(nxt) fused with skel update. grid.z = field*2 + batch (3 fields).
__global__ void __launch_bounds__(256) k_dilup(const float* __restrict__ nxt_base,
                                               const float* __restrict__ cur_base,
                                               float* __restrict__ skel_base, int first) {
    __shared__ float4 wp[4][TH + 2][32];  // w-pooled(max) plane ring, slot = (plane+4)%4
    int lane = threadIdx.x, ty = threadIdx.y;
    int h0 = blockIdx.x * TH;
    int dz = blockIdx.y * CHUNK;
    int f = blockIdx.z >> 1, b = blockIdx.z & 1;
    size_t off = (size_t)f * NT + (size_t)b * SP;
    const float* nxt = nxt_base + off;
    const float* cur = cur_base + off;
    float* skel = skel_base + off;

    store_wp<false>(nxt, dz - 1, wp[(dz + 3) % 4], h0, lane, ty);
    store_wp<false>(nxt, dz,     wp[dz % 4],       h0, lane, ty);
    __syncthreads();
    float4 Pm = hpool3<false>(wp[(dz + 3) % 4], lane, ty);
    float4 P0 = hpool3<false>(wp[dz % 4], lane, ty);

    #pragma unroll
    for (int k = 0; k < CHUNK; k += 2) {
        int d = dz + k;
        store_wp<false>(nxt, d + 1, wp[(d + 1) % 4], h0, lane, ty);
        store_wp<false>(nxt, d + 2, wp[(d + 2) % 4], h0, lane, ty);
        __syncthreads();
        float4 P1 = hpool3<false>(wp[(d + 1) % 4], lane, ty);
        float4 P2 = hpool3<false>(wp[(d + 2) % 4], lane, ty);
        #pragma unroll
        for (int q = 0; q < 2; q++) {
            float4 dil = (q == 0) ? op4<false>(op4<false>(Pm, P0), P1)
                                  : op4<false>(op4<false>(P0, P1), P2);
            size_t ro = (size_t)(d + q) * (HW / 4) + (h0 + ty) * 32 + lane;
            float4 cv = ((const float4*)cur)[ro];
            float4 dl;
            dl.x = fmaxf(cv.x - dil.x, 0.f); dl.y = fmaxf(cv.y - dil.y, 0.f);
            dl.z = fmaxf(cv.z - dil.z, 0.f); dl.w = fmaxf(cv.w - dil.w, 0.f);
            if (first) {
                ((float4*)skel)[ro] = dl;
            } else {
                float4 s = ((float4*)skel)[ro];
                s.x += fmaxf(dl.x - s.x * dl.x, 0.f);
                s.y += fmaxf(dl.y - s.y * dl.y, 0.f);
                s.z += fmaxf(dl.z - s.z * dl.z, 0.f);
                s.w += fmaxf(dl.w - s.w * dl.w, 0.f);
                ((float4*)skel)[ro] = s;
            }
        }
        Pm = P1; P0 = P2;
    }
}

// minpool27 fused with EDT accumulation. grid.z = field*2 + batch (2 fields).
__global__ void __launch_bounds__(256) k_minacc(const float* __restrict__ src_base,
                                                float* __restrict__ dst_base,
                                                float* __restrict__ acc_base) {
    __shared__ float4 wp[4][TH + 2][32];  // w-pooled(min) plane ring
    int lane = threadIdx.x, ty = threadIdx.y;
    int h0 = blockIdx.x * TH;
    int dz = blockIdx.y * CHUNK;
    int f = blockIdx.z >> 1, b = blockIdx.z & 1;
    size_t off = (size_t)f * NT + (size_t)b * SP;
    const float* src = src_base + off;
    float* dst = dst_base + off;
    float* acc = acc_base + off;

    store_wp<true>(src, dz - 1, wp[(dz + 3) % 4], h0, lane, ty);
    store_wp<true>(src, dz,     wp[dz % 4],       h0, lane, ty);
    __syncthreads();
    float4 Pm = hpool3<true>(wp[(dz + 3) % 4], lane, ty);
    float4 P0 = hpool3<true>(wp[dz % 4], lane, ty);

    #pragma unroll
    for (int k = 0; k < CHUNK; k += 2) {
        int d = dz + k;
        store_wp<true>(src, d + 1, wp[(d + 1) % 4], h0, lane, ty);
        store_wp<true>(src, d + 2, wp[(d + 2) % 4], h0, lane, ty);
        __syncthreads();
        float4 P1 = hpool3<true>(wp[(d + 1) % 4], lane, ty);
        float4 P2 = hpool3<true>(wp[(d + 2) % 4], lane, ty);
        #pragma unroll
        for (int q = 0; q < 2; q++) {
            float4 o = (q == 0) ? op4<true>(op4<true>(Pm, P0), P1)
                                : op4<true>(op4<true>(P0, P1), P2);
            size_t ro = (size_t)(d + q) * (HW / 4) + (h0 + ty) * 32 + lane;
            ((float4*)dst)[ro] = o;
            float4 av = ((float4*)acc)[ro];
            av.x += o.x; av.y += o.y; av.z += o.z; av.w += o.w;
            ((float4*)acc)[ro] = av;
        }
        Pm = P1; P0 = P2;
    }
}

// ---------------- reduction helpers (256-thread blocks) ---------------------
__device__ __forceinline__ int flat_tid() { return threadIdx.y * blockDim.x + threadIdx.x; }

__device__ __forceinline__ void block_add(double v, double* dst) {
    int tid = flat_tid();
    for (int o = 16; o; o >>= 1) v += __shfl_down_sync(0xffffffffu, v, o);
    __shared__ double sh[8];
    int lane = tid & 31, wid = tid >> 5;
    if (lane == 0) sh[wid] = v;
    __syncthreads();
    if (wid == 0) {
        double x = (lane < 8) ? sh[lane] : 0.0;
        for (int o = 4; o; o >>= 1) x += __shfl_down_sync(0xffffffffu, x, o);
        if (lane == 0) atomicAdd(dst, x);
    }
    __syncthreads();
}

__device__ __forceinline__ float block_maxv(float v) {
    int tid = flat_tid();
    for (int o = 16; o; o >>= 1) v = fmaxf(v, __shfl_down_sync(0xffffffffu, v, o));
    __shared__ float sh[8];
    int lane = tid & 31, wid = tid >> 5;
    if (lane == 0) sh[wid] = v;
    __syncthreads();
    float r = v;
    if (wid == 0) {
        float x = (lane < 8) ? sh[lane] : -1e30f;
        for (int o = 4; o; o >>= 1) x = fmaxf(x, __shfl_down_sync(0xffffffffu, x, o));
        r = x;
    }
    __syncthreads();
    return r;
}

__device__ __forceinline__ float block_minv(float v) {
    int tid = flat_tid();
    for (int o = 16; o; o >>= 1) v = fminf(v, __shfl_down_sync(0xffffffffu, v, o));
    __shared__ float sh[8];
    int lane = tid & 31, wid = tid >> 5;
    if (lane == 0) sh[wid] = v;
    __syncthreads();
    float r = v;
    if (wid == 0) {
        float x = (lane < 8) ? sh[lane] : 1e30f;
        for (int o = 4; o; o >>= 1) x = fminf(x, __shfl_down_sync(0xffffffffu, x, o));
        r = x;
    }
    __syncthreads();
    return r;
}

// ---------------- pointwise / reduction kernels -------------------------------
__global__ void k_zero() {
    int t = threadIdx.x;
    if (t < 14) g_sum[t] = 0.0;
    if (t < 4) { g_rmx[t] = 0u; g_rmn[t] = 0x7f800000u; }
}

__global__ void k_init(const float* __restrict__ net, const int* __restrict__ tgt) {
    int i = blockIdx.x * blockDim.x + threadIdx.x;
    int b = i / SP, s = i - b * SP;
    float x0 = net[(size_t)(b * 2) * SP + s];
    float x1 = net[(size_t)(b * 2 + 1) * SP + s];
    int t = tgt[i];
    float m = fmaxf(x0, x1);
    float e0 = expf(x0 - m), e1 = expf(x1 - m);
    float z = e0 + e1;
    float p1 = e1 / z;
    float yv = (t > 0) ? 1.f : 0.f;
    float hd = (p1 > 0.5f) ? 1.f : 0.f;
    g_P[i] = p1; g_Y[i] = yv; g_H[i] = hd;
    g_A[i] = p1; g_A[NT + i] = yv; g_A[2 * NT + i] = hd;
    float lse = m + logf(z);
    float ce = -(((t > 0) ? x1 : x0) - lse);
    float conn = fabsf(((x0 > 0.5f) ? 1.f : 0.f) - yv) + fabsf(((x1 > 0.5f) ? 1.f : 0.f) - yv);
    block_add((double)p1,        &g_sum[0]);
    block_add((double)yv,        &g_sum[1]);
    block_add((double)(p1 * yv), &g_sum[2]);
    block_add((double)ce,        &g_sum[3]);
    block_add((double)conn,      &g_sum[4]);
}

__global__ void k_edtinit() {
    int i = blockIdx.x * blockDim.x + threadIdx.x;  // i in [0, 2*NT)
    float v = (i < NT) ? g_Y[i] : g_H[i - NT];
    g_EA[i] = v;
    g_ACC[i] = v;
}

__global__ void k_sobel(const float* __restrict__ net, const int* __restrict__ tgt) {
    int w = blockIdx.x * blockDim.x + threadIdx.x;
    int h = blockIdx.y * blockDim.y + threadIdx.y;
    int z = blockIdx.z;
    int b = z / DD, d = z - b * DD;
    const float smw[3] = {1.f, 2.f, 1.f};
    const float grw[3] = {-1.f, 0.f, 1.f};
    float gx = 0.f, gy = 0.f, gz = 0.f, tx = 0.f, ty = 0.f, tz = 0.f;
    const float* p0 = net + (size_t)(b * 2) * SP;
    const int*   tb = tgt + (size_t)b * SP;
    #pragma unroll
    for (int dd = -1; dd <= 1; dd++) {
        int dn = d + dd; if (dn < 0 || dn >= DD) continue;
        #pragma unroll
        for (int hh = -1; hh <= 1; hh++) {
            int hn = h + hh; if (hn < 0 || hn >= HH) continue;
            #pragma unroll
            for (int ww = -1; ww <= 1; ww++) {
                int wn = w + ww; if (wn < 0 || wn >= WW) continue;
                int o = dn * HW + hn * WW + wn;
                float v  = p0[o];
                float tv = (float)tb[o];
                float ca = smw[hh + 1] * grw[ww + 1];
                float cb = smw[dd + 1] * grw[ww + 1];
                float cc = smw[dd + 1] * grw[hh + 1];
                gx += v * ca;  gy += v * cb;  gz += v * cc;
                tx += tv * ca; ty += tv * cb; tz += tv * cc;
            }
        }
    }
    float npn = sqrtf(gx * gx + gy * gy + gz * gz);
    float ia = 1.f / fmaxf(npn, 1e-12f);
    float px = gx * ia, py = gy * ia, pz = gz * ia;
    float ntn = sqrtf(tx * tx + ty * ty + tz * tz);
    float ib = 1.f / fmaxf(ntn, 1e-12f);
    float qx = tx * ib, qy = ty * ib, qz = tz * ib;
    float num = px * qx + py * qy + pz * qz;
    float den = fmaxf(sqrtf(px * px + py * py + pz * pz) *
                      sqrtf(qx * qx + qy * qy + qz * qz), 1e-8f);
    block_add((double)(num / den), &g_sum[5]);
}

__global__ void k_radius() {
    int i = blockIdx.x * 256 + threadIdx.x;
    int b = i / SP;
    float radl = g_ACC[i] * g_Y[i] * g_S[NT + i];
    float spp  = g_S[2 * NT + i] * g_P[i];
    float sb   = (spp > 0.5f) ? 1.f : 0.f;
    float radp = g_ACC[NT + i] * g_H[i] * sb;
    float mxl = block_maxv(radl);
    float mnl = block_minv(radl);
    float mxp = block_maxv(radp);
    float mnp = block_minv(radp);
    if (flat_tid() == 0) {
        atomicMax(&g_rmx[b],     __float_as_uint(mxl));
        atomicMin(&g_rmn[b],     __float_as_uint(mnl));
        atomicMax(&g_rmx[2 + b], __float_as_uint(mxp));
        atomicMin(&g_rmn[2 + b], __float_as_uint(mnp));
    }
}

__global__ void k_final() {
    int i = blockIdx.x * 256 + threadIdx.x;
    int b = i / SP;
    float spv = g_S[i];
    float st  = g_S[NT + i];
    float y   = g_Y[i];
    float p   = g_P[i];
    float hd  = g_H[i];
    float sh  = g_S[2 * NT + i];

    float rmaxl = fmaxf(__uint_as_float(g_rmx[b]), 1.f);
    float rminl = fmaxf(__uint_as_float(g_rmn[b]), 1.f);
    float rmaxp = fmaxf(__uint_as_float(g_rmx[2 + b]), 1.f);
    float rminp = fmaxf(__uint_as_float(g_rmn[2 + b]), 1.f);

    float distl = g_ACC[i] * y;
    float qvl = fminf(distl, rmaxl) / rmaxl * y;
    float radl = distl * st;
    float il = (rmaxl - radl + rminl) / rmaxl; il *= il;
    float qsl = il * st * st;

    float spp = sh * p;
    float sb  = (spp > 0.5f) ? 1.f : 0.f;
    float distp = g_ACC[NT + i] * hd;
    float qvp = fminf(distp, rmaxp) / rmaxp * p;
    float radp = distp * sb;
    float ip = (rmaxp - radp + rminp) / rmaxp; ip *= ip;
    float qsp = ip * sb * spp;

    float inter1 = qsp * powf(qsp + 1e-4f, 0.7f) * qvl;
    float union1 = qsp * (0.1f * qsp + 0.9f * qvl);
    float inter2 = qsl * powf(qvp + 1e-4f, 0.7f) * qsl;
    float union2 = qsl * (0.1f * qvp + 0.9f * qsl);

    block_add((double)(spv * y), &g_sum[6]);
    block_add((double)spv,       &g_sum[7]);
    block_add((double)(st * p),  &g_sum[8]);
    block_add((double)st,        &g_sum[9]);
    block_add((double)inter1,    &g_sum[10]);
    block_add((double)union1,    &g_sum[11]);
    block_add((double)inter2,    &g_sum[12]);
    block_add((double)union2,    &g_sum[13]);
}

__global__ void k_combine(float* out) {
    double tp = g_sum[2];
    double fp = g_sum[0] - tp;
    double fn = g_sum[1] - tp;
    double dice = -((2.0 * tp + 1e-5) / (2.0 * tp + fp + fn + 1e-5));
    double ce   = g_sum[3] / (double)NT;
    double tprec = (g_sum[6] + 1.0) / (g_sum[7] + 1.0);
    double tsens = (g_sum[8] + 1.0) / (g_sum[9] + 1.0);
    double cl = 1.0 - 2.0 * tprec * tsens / (tprec + tsens);
    double dir  = 1.0 - g_sum[5] / (double)NT;
    double conn = g_sum[4] / (2.0 * (double)NT);
    double u1 = 1.0 - (g_sum[10] + 1.0) / (g_sum[11] + 1.0);
    double u2 = 1.0 - (g_sum[12] + 1.0) / (g_sum[13] + 1.0);
    out[0] = (float)(dice + ce + cl + dir + conn + u1 + u2);
}

// ---------------- host orchestration ----------------------------------------
extern "C" void kernel_launch(void* const* d_in, const int* in_sizes, int n_in,
                              void* d_out, int out_size) {
    (void)in_sizes; (void)n_in; (void)out_size;
    const float* net = (const float*)d_in[0];
    const int*   tgt = (const int*)d_in[1];
    float* out = (float*)d_out;

    float *A, *Bp, *S, *EA, *EB, *ACC;
    cudaGetSymbolAddress((void**)&A,   g_A);
    cudaGetSymbolAddress((void**)&Bp,  g_B);
    cudaGetSymbolAddress((void**)&S,   g_S);
    cudaGetSymbolAddress((void**)&EA,  g_EA);
    cudaGetSymbolAddress((void**)&EB,  g_EB);
    cudaGetSymbolAddress((void**)&ACC, g_ACC);

    dim3 blk(32, TH, 1);
    dim3 grd3(HH / TH, DD / CHUNK, 3 * BB);   // skel: 16 x 8 x 6 = 768 blocks
    dim3 grd2(HH / TH, DD / CHUNK, 2 * BB);   // edt:  16 x 8 x 4 = 512 blocks
    dim3 sblk(32, 8, 1), sgrd(WW / 32, HH / 8, BB * DD);

    k_zero<<<1, 32>>>();
    k_init<<<NT / 256, 256>>>(net, tgt);
    k_sobel<<<sgrd, sblk>>>(net, tgt);

    // three soft_skels, batched (fields: prob, y_true, hard), 11 iterations
    k_erode<<<grd3, blk>>>(A, Bp);
    k_dilup<<<grd3, blk>>>(Bp, A, S, 1);
    float* cur = Bp; float* oth = A;
    for (int it = 0; it < 10; it++) {
        k_erode<<<grd3, blk>>>(cur, oth);
        k_dilup<<<grd3, blk>>>(oth, cur, S, 0);
        float* t = cur; cur = oth; oth = t;
    }

    // two EDT scans, batched (fields: y_true, hard)
    k_edtinit<<<2 * NT / 256, 256>>>();
    float* ec = EA; float* eo = EB;
    for (int k = 0; k < 15; k++) {
        k_minacc<<<grd2, blk>>>(ec, eo, ACC);
        float* t = ec; ec = eo; eo = t;
    }

    k_radius<<<NT / 256, 256>>>();
    k_final<<<NT / 256, 256>>>();
    k_combine<<<1, 1>>>(out);
}